// round 2
// baseline (speedup 1.0000x reference)
#include <cuda_runtime.h>
#include <math.h>

#define B 8
#define N 1024
#define H 16
#define D 64
#define HD 1024

// Scratch (allocation-free): Q,K,V in [B,H,N,D]; RB = rel+rel_2d combined bias.
__device__ float g_Q[B * H * N * D];
__device__ float g_K[B * H * N * D];
__device__ float g_V[B * H * N * D];
__device__ float g_RB[H * N * N];

// ---------------------------------------------------------------------------
// Kernel 0: combined bias = rel_pos + rel_2d_pos  (16M floats)
// ---------------------------------------------------------------------------
__global__ __launch_bounds__(256) void bias_kernel(
    const float* __restrict__ rel, const float* __restrict__ rel2)
{
    size_t i = ((size_t)blockIdx.x * 256 + threadIdx.x) * 4;
    float4 a = *(const float4*)&rel[i];
    float4 b = *(const float4*)&rel2[i];
    a.x += b.x; a.y += b.y; a.z += b.z; a.w += b.w;
    *(float4*)&g_RB[i] = a;
}

// ---------------------------------------------------------------------------
// Kernel 1: fused QKV projection. 128x128 tile, BK=16, 256 threads, 8x8
// microtile, double-buffered smem (A,B stored k-major for vector frag loads).
// ---------------------------------------------------------------------------
__global__ __launch_bounds__(256) void qkv_kernel(
    const float* __restrict__ hs,   // [B*N, HD]
    const float* __restrict__ w,    // [3*HD, HD]
    const float* __restrict__ qb,   // [HD]
    const float* __restrict__ vb)   // [HD]
{
    __shared__ float As[2][16][136];
    __shared__ float Bs[2][16][136];

    const int tid = threadIdx.x;
    const int tx = tid & 15;
    const int ty = tid >> 4;
    const int m0 = blockIdx.y * 128;
    const int n0 = blockIdx.x * 128;

    const int lr = tid >> 2;        // load row 0..63 (two passes -> 128 rows)
    const int lc = (tid & 3) * 4;   // load col 0..12

    float acc[8][8];
#pragma unroll
    for (int i = 0; i < 8; i++)
#pragma unroll
        for (int j = 0; j < 8; j++) acc[i][j] = 0.0f;

    float4 aR[2], bR[2];

    // prologue: load chunk 0
#pragma unroll
    for (int p = 0; p < 2; p++) {
        int r = lr + p * 64;
        aR[p] = *(const float4*)&hs[(size_t)(m0 + r) * HD + lc];
        bR[p] = *(const float4*)&w[(size_t)(n0 + r) * HD + lc];
    }
#pragma unroll
    for (int p = 0; p < 2; p++) {
        int r = lr + p * 64;
        As[0][lc + 0][r] = aR[p].x; As[0][lc + 1][r] = aR[p].y;
        As[0][lc + 2][r] = aR[p].z; As[0][lc + 3][r] = aR[p].w;
        Bs[0][lc + 0][r] = bR[p].x; Bs[0][lc + 1][r] = bR[p].y;
        Bs[0][lc + 2][r] = bR[p].z; Bs[0][lc + 3][r] = bR[p].w;
    }
    __syncthreads();

    for (int kc = 0; kc < 64; kc++) {
        const int buf = kc & 1;
        if (kc < 63) {
            const int k0 = (kc + 1) * 16;
#pragma unroll
            for (int p = 0; p < 2; p++) {
                int r = lr + p * 64;
                aR[p] = *(const float4*)&hs[(size_t)(m0 + r) * HD + k0 + lc];
                bR[p] = *(const float4*)&w[(size_t)(n0 + r) * HD + k0 + lc];
            }
        }

#pragma unroll
        for (int k = 0; k < 16; k++) {
            float4 a0 = *(float4*)&As[buf][k][ty * 8];
            float4 a1 = *(float4*)&As[buf][k][ty * 8 + 4];
            float4 b0 = *(float4*)&Bs[buf][k][tx * 8];
            float4 b1 = *(float4*)&Bs[buf][k][tx * 8 + 4];
            float av[8] = {a0.x, a0.y, a0.z, a0.w, a1.x, a1.y, a1.z, a1.w};
            float bv[8] = {b0.x, b0.y, b0.z, b0.w, b1.x, b1.y, b1.z, b1.w};
#pragma unroll
            for (int i = 0; i < 8; i++)
#pragma unroll
                for (int j = 0; j < 8; j++)
                    acc[i][j] += av[i] * bv[j];
        }

        if (kc < 63) {
            const int nb = buf ^ 1;
#pragma unroll
            for (int p = 0; p < 2; p++) {
                int r = lr + p * 64;
                As[nb][lc + 0][r] = aR[p].x; As[nb][lc + 1][r] = aR[p].y;
                As[nb][lc + 2][r] = aR[p].z; As[nb][lc + 3][r] = aR[p].w;
                Bs[nb][lc + 0][r] = bR[p].x; Bs[nb][lc + 1][r] = bR[p].y;
                Bs[nb][lc + 2][r] = bR[p].z; Bs[nb][lc + 3][r] = bR[p].w;
            }
            __syncthreads();
        }
    }

    // epilogue: scatter to Q/K/V head-major scratch with fused biases
#pragma unroll
    for (int i = 0; i < 8; i++) {
        int m = m0 + ty * 8 + i;
        int b = m >> 10;
        int n = m & 1023;
#pragma unroll
        for (int j = 0; j < 8; j++) {
            int o = n0 + tx * 8 + j;         // [0, 3072)
            int seg = o >> 10;
            int hd = o & 1023;
            int h = hd >> 6;
            int d = hd & 63;
            size_t idx = (((size_t)(b * H + h)) * N + n) * D + d;
            float val = acc[i][j];
            if (seg == 0)       g_Q[idx] = (val + qb[hd]) * 0.125f;   // 1/sqrt(64)
            else if (seg == 1)  g_K[idx] = val;
            else                g_V[idx] = val + vb[hd];
        }
    }
}

// ---------------------------------------------------------------------------
// Kernel 2: flash attention with precombined bias + mask-replace (1e-8).
// 64q x 64k tiles, 4x4 microtile, V kept TRANSPOSED in smem -> LDS.128 PV.
// ---------------------------------------------------------------------------
__global__ __launch_bounds__(256) void attn_kernel(
    const int*   __restrict__ mask,  // [B, N]
    float*       __restrict__ out)   // [B, N, HD]
{
    __shared__ float Qs[64][68];
    __shared__ float Ks[64][68];
    __shared__ float Vt[64][68];   // [d][m]  (transposed V)
    __shared__ float Ps[64][68];   // [q][m]
    __shared__ int   msk[N];

    const int tid = threadIdx.x;
    const int tx = tid & 15;
    const int ty = tid >> 4;
    const int q0 = blockIdx.x * 64;
    const int h  = blockIdx.y;
    const int b  = blockIdx.z;

    const float* Qg = g_Q + (((size_t)(b * H + h)) * N) * D;
    const float* Kg = g_K + (((size_t)(b * H + h)) * N) * D;
    const float* Vg = g_V + (((size_t)(b * H + h)) * N) * D;
    const float* rb = g_RB + (size_t)h * N * N;

    const int lr = tid >> 4;        // 0..15 (x4 passes -> 64 rows)
    const int lc = (tid & 15) * 4;  // 0..60

#pragma unroll
    for (int p = 0; p < 4; p++) {
        int r = lr + p * 16;
        *(float4*)&Qs[r][lc] = *(const float4*)&Qg[(size_t)(q0 + r) * D + lc];
    }
    for (int i = tid; i < N; i += 256) msk[i] = mask[b * N + i];
    __syncthreads();

    float m_i[4], l_i[4], o_acc[4][4];
#pragma unroll
    for (int i = 0; i < 4; i++) {
        m_i[i] = -INFINITY;
        l_i[i] = 0.0f;
#pragma unroll
        for (int j = 0; j < 4; j++) o_acc[i][j] = 0.0f;
    }

    for (int t = 0; t < 16; t++) {
        const int k0 = t * 64;
#pragma unroll
        for (int p = 0; p < 4; p++) {
            int r = lr + p * 16;
            *(float4*)&Ks[r][lc] = *(const float4*)&Kg[(size_t)(k0 + r) * D + lc];
            float4 v = *(const float4*)&Vg[(size_t)(k0 + r) * D + lc];
            Vt[lc + 0][r] = v.x; Vt[lc + 1][r] = v.y;
            Vt[lc + 2][r] = v.z; Vt[lc + 3][r] = v.w;
        }
        __syncthreads();

        // S = Q @ K^T
        float s[4][4];
#pragma unroll
        for (int i = 0; i < 4; i++)
#pragma unroll
            for (int j = 0; j < 4; j++) s[i][j] = 0.0f;

#pragma unroll
        for (int kk = 0; kk < 64; kk += 4) {
            float4 a[4], bb[4];
#pragma unroll
            for (int i = 0; i < 4; i++) a[i] = *(float4*)&Qs[ty + 16 * i][kk];
#pragma unroll
            for (int j = 0; j < 4; j++) bb[j] = *(float4*)&Ks[tx + 16 * j][kk];
#pragma unroll
            for (int i = 0; i < 4; i++)
#pragma unroll
                for (int j = 0; j < 4; j++) {
                    s[i][j] += a[i].x * bb[j].x;
                    s[i][j] += a[i].y * bb[j].y;
                    s[i][j] += a[i].z * bb[j].z;
                    s[i][j] += a[i].w * bb[j].w;
                }
        }

        // combined bias + mask
#pragma unroll
        for (int i = 0; i < 4; i++) {
            int qg = q0 + ty + 16 * i;
#pragma unroll
            for (int j = 0; j < 4; j++) {
                int kg = k0 + tx + 16 * j;
                float sv = s[i][j] + rb[(size_t)qg * N + kg];
                if (msk[kg] != 0) sv = 1e-8f;
                s[i][j] = sv;
            }
        }

        // online softmax
#pragma unroll
        for (int i = 0; i < 4; i++) {
            float rmax = fmaxf(fmaxf(s[i][0], s[i][1]), fmaxf(s[i][2], s[i][3]));
#pragma unroll
            for (int off = 8; off > 0; off >>= 1)
                rmax = fmaxf(rmax, __shfl_xor_sync(0xffffffffu, rmax, off));
            float mn = fmaxf(m_i[i], rmax);
            float scale = __expf(m_i[i] - mn);
            m_i[i] = mn;

            float rsum = 0.0f;
#pragma unroll
            for (int j = 0; j < 4; j++) {
                float p = __expf(s[i][j] - mn);
                rsum += p;
                Ps[ty + 16 * i][tx + 16 * j] = p;
            }
#pragma unroll
            for (int off = 8; off > 0; off >>= 1)
                rsum += __shfl_xor_sync(0xffffffffu, rsum, off);
            l_i[i] = l_i[i] * scale + rsum;
#pragma unroll
            for (int j = 0; j < 4; j++) o_acc[i][j] *= scale;
        }
        __syncthreads();

        // O += P @ V  via transposed V: dot-4 along m, all LDS.128
#pragma unroll
        for (int mm = 0; mm < 64; mm += 4) {
            float4 pv[4], vt[4];
#pragma unroll
            for (int i = 0; i < 4; i++) pv[i] = *(float4*)&Ps[ty + 16 * i][mm];
#pragma unroll
            for (int j = 0; j < 4; j++) vt[j] = *(float4*)&Vt[tx + 16 * j][mm];
#pragma unroll
            for (int i = 0; i < 4; i++)
#pragma unroll
                for (int j = 0; j < 4; j++) {
                    o_acc[i][j] += pv[i].x * vt[j].x;
                    o_acc[i][j] += pv[i].y * vt[j].y;
                    o_acc[i][j] += pv[i].z * vt[j].z;
                    o_acc[i][j] += pv[i].w * vt[j].w;
                }
        }
        __syncthreads();
    }

    // finalize
#pragma unroll
    for (int i = 0; i < 4; i++) {
        int n = q0 + ty + 16 * i;
        float inv = 1.0f / l_i[i];
#pragma unroll
        for (int j = 0; j < 4; j++) {
            int d = tx + 16 * j;
            out[((size_t)b * N + n) * HD + h * D + d] = o_acc[i][j] * inv;
        }
    }
}

extern "C" void kernel_launch(void* const* d_in, const int* in_sizes, int n_in,
                              void* d_out, int out_size)
{
    (void)in_sizes; (void)n_in; (void)out_size;
    const float* hs   = (const float*)d_in[0];
    const float* w    = (const float*)d_in[1];
    const float* qb   = (const float*)d_in[2];
    const float* vb   = (const float*)d_in[3];
    const float* rel  = (const float*)d_in[4];
    const float* rel2 = (const float*)d_in[5];
    const int*   mask = (const int*)d_in[6];
    float* out = (float*)d_out;

    bias_kernel<<<(H * N * N) / (256 * 4), 256>>>(rel, rel2);

    dim3 g1(3 * HD / 128, (B * N) / 128);        // (24, 64)
    qkv_kernel<<<g1, 256>>>(hs, w, qb, vb);

    dim3 g2(N / 64, H, B);                       // (16, 16, 8)
    attn_kernel<<<g2, 256>>>(mask, out);
}

// round 3
// speedup vs baseline: 1.9364x; 1.9364x over previous
#include <cuda_runtime.h>
#include <math.h>
#include <stdint.h>

#define B 8
#define N 1024
#define H 16
#define D 64
#define HD 1024

// Scratch (allocation-free)
__device__ float g_Q[B * H * N * D];
__device__ float g_K[B * H * N * D];
__device__ float g_V[B * H * N * D];
__device__ float g_RB[H * N * N];

__device__ __forceinline__ uint32_t f2tf(float f) {
    uint32_t u;
    asm("cvt.rna.tf32.f32 %0, %1;" : "=r"(u) : "f"(f));
    return u;
}

__device__ __forceinline__ void mma8(float* d, const uint32_t* a, const uint32_t* b) {
    asm volatile(
        "mma.sync.aligned.m16n8k8.row.col.f32.tf32.tf32.f32 "
        "{%0,%1,%2,%3}, {%4,%5,%6,%7}, {%8,%9}, {%0,%1,%2,%3};"
        : "+f"(d[0]), "+f"(d[1]), "+f"(d[2]), "+f"(d[3])
        : "r"(a[0]), "r"(a[1]), "r"(a[2]), "r"(a[3]), "r"(b[0]), "r"(b[1]));
}

// ---------------------------------------------------------------------------
// Kernel 0: combined bias = rel_pos + rel_2d_pos
// ---------------------------------------------------------------------------
__global__ __launch_bounds__(256) void bias_kernel(
    const float* __restrict__ rel, const float* __restrict__ rel2)
{
    size_t i = ((size_t)blockIdx.x * 256 + threadIdx.x) * 4;
    float4 a = *(const float4*)&rel[i];
    float4 b = *(const float4*)&rel2[i];
    a.x += b.x; a.y += b.y; a.z += b.z; a.w += b.w;
    *(float4*)&g_RB[i] = a;
}

// ---------------------------------------------------------------------------
// Kernel 1: QKV projection via TF32 mma. D[o][token] = W[o][k] * hs[token][k]^T
// CTA: 128(o) x 128(token), 8 warps (2x4), warp tile 64x32, BK=16 dbl-buffered.
// ---------------------------------------------------------------------------
__global__ __launch_bounds__(256) void qkv_kernel(
    const float* __restrict__ hs,   // [8192, 1024]
    const float* __restrict__ w,    // [3072, 1024]
    const float* __restrict__ qb,
    const float* __restrict__ vb)
{
    __shared__ uint32_t Ws[2][128][20];
    __shared__ uint32_t Hs[2][128][20];

    const int tid  = threadIdx.x;
    const int lane = tid & 31;
    const int warp = tid >> 5;
    const int wo = (warp >> 2) * 64;   // warp o-offset
    const int wt = (warp & 3) * 32;    // warp token-offset
    const int o0 = blockIdx.x * 128;
    const int t0 = blockIdx.y * 128;

    const int lrow = tid >> 1;         // 0..127
    const int lk   = (tid & 1) * 8;    // 0 or 8

    float acc[4][4][4];
#pragma unroll
    for (int mi = 0; mi < 4; mi++)
#pragma unroll
        for (int nj = 0; nj < 4; nj++)
#pragma unroll
            for (int q = 0; q < 4; q++) acc[mi][nj][q] = 0.0f;

    const float* wp = w  + (size_t)(o0 + lrow) * HD + lk;
    const float* hp = hs + (size_t)(t0 + lrow) * HD + lk;

    float4 f0, f1, g0, g1;
    f0 = *(const float4*)(wp);     f1 = *(const float4*)(wp + 4);
    g0 = *(const float4*)(hp);     g1 = *(const float4*)(hp + 4);

    {
        uint32_t* wr = &Ws[0][lrow][lk];
        wr[0] = f2tf(f0.x); wr[1] = f2tf(f0.y); wr[2] = f2tf(f0.z); wr[3] = f2tf(f0.w);
        wr[4] = f2tf(f1.x); wr[5] = f2tf(f1.y); wr[6] = f2tf(f1.z); wr[7] = f2tf(f1.w);
        uint32_t* hr = &Hs[0][lrow][lk];
        hr[0] = f2tf(g0.x); hr[1] = f2tf(g0.y); hr[2] = f2tf(g0.z); hr[3] = f2tf(g0.w);
        hr[4] = f2tf(g1.x); hr[5] = f2tf(g1.y); hr[6] = f2tf(g1.z); hr[7] = f2tf(g1.w);
    }
    __syncthreads();

    const int r = lane >> 2;
    const int c = lane & 3;

    for (int kc = 0; kc < 64; kc++) {
        const int buf = kc & 1;
        if (kc < 63) {
            const int kb = (kc + 1) * 16;
            f0 = *(const float4*)(wp + kb);     f1 = *(const float4*)(wp + kb + 4);
            g0 = *(const float4*)(hp + kb);     g1 = *(const float4*)(hp + kb + 4);
        }

#pragma unroll
        for (int ks = 0; ks < 2; ks++) {
            const int kk = ks * 8;
            uint32_t a[4][4], bb[4][2];
#pragma unroll
            for (int mi = 0; mi < 4; mi++) {
                int row = wo + 16 * mi + r;
                a[mi][0] = Ws[buf][row][kk + c];
                a[mi][1] = Ws[buf][row + 8][kk + c];
                a[mi][2] = Ws[buf][row][kk + c + 4];
                a[mi][3] = Ws[buf][row + 8][kk + c + 4];
            }
#pragma unroll
            for (int nj = 0; nj < 4; nj++) {
                int col = wt + 8 * nj + r;
                bb[nj][0] = Hs[buf][col][kk + c];
                bb[nj][1] = Hs[buf][col][kk + c + 4];
            }
#pragma unroll
            for (int mi = 0; mi < 4; mi++)
#pragma unroll
                for (int nj = 0; nj < 4; nj++)
                    mma8(acc[mi][nj], a[mi], bb[nj]);
        }

        if (kc < 63) {
            const int nb = buf ^ 1;
            uint32_t* wr = &Ws[nb][lrow][lk];
            wr[0] = f2tf(f0.x); wr[1] = f2tf(f0.y); wr[2] = f2tf(f0.z); wr[3] = f2tf(f0.w);
            wr[4] = f2tf(f1.x); wr[5] = f2tf(f1.y); wr[6] = f2tf(f1.z); wr[7] = f2tf(f1.w);
            uint32_t* hr = &Hs[nb][lrow][lk];
            hr[0] = f2tf(g0.x); hr[1] = f2tf(g0.y); hr[2] = f2tf(g0.z); hr[3] = f2tf(g0.w);
            hr[4] = f2tf(g1.x); hr[5] = f2tf(g1.y); hr[6] = f2tf(g1.z); hr[7] = f2tf(g1.w);
            __syncthreads();
        }
    }

    // epilogue: scatter, fused q/v biases, token pairs -> +D stride
    const int c2 = c * 2;
#pragma unroll
    for (int mi = 0; mi < 4; mi++) {
#pragma unroll
        for (int rr = 0; rr < 2; rr++) {
            int o = o0 + wo + 16 * mi + r + 8 * rr;
            int seg = o >> 10, hd = o & 1023, h = hd >> 6, d = hd & 63;
#pragma unroll
            for (int nj = 0; nj < 4; nj++) {
                int tok = t0 + wt + 8 * nj + c2;
                int b_ = tok >> 10, n = tok & 1023;
                size_t idx = (((size_t)(b_ * H + h)) * N + n) * D + d;
                float v0 = acc[mi][nj][rr * 2 + 0];
                float v1 = acc[mi][nj][rr * 2 + 1];
                if (seg == 0) {
                    float qv = qb[hd];
                    g_Q[idx] = (v0 + qv) * 0.125f;
                    g_Q[idx + D] = (v1 + qv) * 0.125f;
                } else if (seg == 1) {
                    g_K[idx] = v0;
                    g_K[idx + D] = v1;
                } else {
                    float vv = vb[hd];
                    g_V[idx] = v0 + vv;
                    g_V[idx + D] = v1 + vv;
                }
            }
        }
    }
}

// ---------------------------------------------------------------------------
// Kernel 2: flash attention via TF32 mma. CTA: 64 q-rows, 4 warps (16 q each).
// 16 key tiles of 64. K tile smem aliased with P tile.
// ---------------------------------------------------------------------------
__global__ __launch_bounds__(128) void attn_kernel(
    const int* __restrict__ mask,
    float*     __restrict__ out)
{
    __shared__ uint32_t KP[64][68];   // K tile, then aliased as P tile
    __shared__ uint32_t Vs[64][72];

    const int tid  = threadIdx.x;
    const int lane = tid & 31;
    const int warp = tid >> 5;
    const int q0 = blockIdx.x * 64;
    const int h  = blockIdx.y;
    const int b  = blockIdx.z;
    const int qw = warp * 16;
    const int r = lane >> 2;
    const int c = lane & 3;

    const float* Qg = g_Q + ((size_t)(b * H + h) * N) * D;
    const float* Kg = g_K + ((size_t)(b * H + h) * N) * D;
    const float* Vg = g_V + ((size_t)(b * H + h) * N) * D;
    const float* rb = g_RB + (size_t)h * N * N;
    const int*   mk = mask + b * N;

    // stage Q tile -> KP (tf32), then lift fragments to registers
    {
        int row = tid >> 1;
        int cb = (tid & 1) * 32;
#pragma unroll
        for (int j = 0; j < 8; j++) {
            float4 v = *(const float4*)&Qg[(size_t)(q0 + row) * D + cb + j * 4];
            uint32_t* p = &KP[row][cb + j * 4];
            p[0] = f2tf(v.x); p[1] = f2tf(v.y); p[2] = f2tf(v.z); p[3] = f2tf(v.w);
        }
    }
    __syncthreads();

    uint32_t qa[8][4];
#pragma unroll
    for (int ks = 0; ks < 8; ks++) {
        qa[ks][0] = KP[qw + r][8 * ks + c];
        qa[ks][1] = KP[qw + r + 8][8 * ks + c];
        qa[ks][2] = KP[qw + r][8 * ks + c + 4];
        qa[ks][3] = KP[qw + r + 8][8 * ks + c + 4];
    }

    float m0v = -INFINITY, m1v = -INFINITY, l0 = 0.0f, l1 = 0.0f;
    float oacc[8][4];
#pragma unroll
    for (int nb = 0; nb < 8; nb++)
#pragma unroll
        for (int q = 0; q < 4; q++) oacc[nb][q] = 0.0f;

    for (int t = 0; t < 16; t++) {
        const int k0 = t * 64;
        __syncthreads();   // prior PV reads (and Q frag reads) complete

        // load K, V tiles (tf32)
        {
            int row = tid >> 1;
            int cb = (tid & 1) * 32;
#pragma unroll
            for (int j = 0; j < 8; j++) {
                float4 kv = *(const float4*)&Kg[(size_t)(k0 + row) * D + cb + j * 4];
                uint32_t* p = &KP[row][cb + j * 4];
                p[0] = f2tf(kv.x); p[1] = f2tf(kv.y); p[2] = f2tf(kv.z); p[3] = f2tf(kv.w);
                float4 vv = *(const float4*)&Vg[(size_t)(k0 + row) * D + cb + j * 4];
                uint32_t* pv = &Vs[row][cb + j * 4];
                pv[0] = f2tf(vv.x); pv[1] = f2tf(vv.y); pv[2] = f2tf(vv.z); pv[3] = f2tf(vv.w);
            }
        }
        __syncthreads();

        // S = Q @ K^T
        float sacc[8][4];
#pragma unroll
        for (int nb = 0; nb < 8; nb++)
#pragma unroll
            for (int q = 0; q < 4; q++) sacc[nb][q] = 0.0f;

#pragma unroll
        for (int ks = 0; ks < 8; ks++) {
            uint32_t bb[8][2];
#pragma unroll
            for (int nb = 0; nb < 8; nb++) {
                bb[nb][0] = KP[8 * nb + r][8 * ks + c];
                bb[nb][1] = KP[8 * nb + r][8 * ks + c + 4];
            }
#pragma unroll
            for (int nb = 0; nb < 8; nb++) mma8(sacc[nb], qa[ks], bb[nb]);
        }

        // bias + mask + row max
        const int row0 = q0 + qw + r;
        float rmax0 = -INFINITY, rmax1 = -INFINITY;
#pragma unroll
        for (int nb = 0; nb < 8; nb++) {
            int col = k0 + 8 * nb + 2 * c;
            float2 bz0 = *(const float2*)&rb[(size_t)row0 * N + col];
            float2 bz1 = *(const float2*)&rb[(size_t)(row0 + 8) * N + col];
            int2 mm = *(const int2*)&mk[col];
            float s0 = sacc[nb][0] + bz0.x; if (mm.x) s0 = 1e-8f;
            float s1 = sacc[nb][1] + bz0.y; if (mm.y) s1 = 1e-8f;
            float s2 = sacc[nb][2] + bz1.x; if (mm.x) s2 = 1e-8f;
            float s3 = sacc[nb][3] + bz1.y; if (mm.y) s3 = 1e-8f;
            sacc[nb][0] = s0; sacc[nb][1] = s1; sacc[nb][2] = s2; sacc[nb][3] = s3;
            rmax0 = fmaxf(rmax0, fmaxf(s0, s1));
            rmax1 = fmaxf(rmax1, fmaxf(s2, s3));
        }
        rmax0 = fmaxf(rmax0, __shfl_xor_sync(0xffffffffu, rmax0, 1));
        rmax0 = fmaxf(rmax0, __shfl_xor_sync(0xffffffffu, rmax0, 2));
        rmax1 = fmaxf(rmax1, __shfl_xor_sync(0xffffffffu, rmax1, 1));
        rmax1 = fmaxf(rmax1, __shfl_xor_sync(0xffffffffu, rmax1, 2));

        float mn0 = fmaxf(m0v, rmax0), mn1 = fmaxf(m1v, rmax1);
        float sc0 = __expf(m0v - mn0), sc1 = __expf(m1v - mn1);
        m0v = mn0; m1v = mn1;

        __syncthreads();   // all warps done reading K -> safe to write P

        float rs0 = 0.0f, rs1 = 0.0f;
#pragma unroll
        for (int nb = 0; nb < 8; nb++) {
            float p0 = __expf(sacc[nb][0] - mn0);
            float p1 = __expf(sacc[nb][1] - mn0);
            float p2 = __expf(sacc[nb][2] - mn1);
            float p3 = __expf(sacc[nb][3] - mn1);
            rs0 += p0 + p1;
            rs1 += p2 + p3;
            int col = 8 * nb + 2 * c;
            uint2 u0; u0.x = f2tf(p0); u0.y = f2tf(p1);
            *(uint2*)&KP[qw + r][col] = u0;
            uint2 u1; u1.x = f2tf(p2); u1.y = f2tf(p3);
            *(uint2*)&KP[qw + r + 8][col] = u1;
        }
        rs0 += __shfl_xor_sync(0xffffffffu, rs0, 1);
        rs0 += __shfl_xor_sync(0xffffffffu, rs0, 2);
        rs1 += __shfl_xor_sync(0xffffffffu, rs1, 1);
        rs1 += __shfl_xor_sync(0xffffffffu, rs1, 2);
        l0 = l0 * sc0 + rs0;
        l1 = l1 * sc1 + rs1;
#pragma unroll
        for (int nb = 0; nb < 8; nb++) {
            oacc[nb][0] *= sc0; oacc[nb][1] *= sc0;
            oacc[nb][2] *= sc1; oacc[nb][3] *= sc1;
        }
        __syncthreads();   // P visible to all warps

        // O += P @ V
#pragma unroll
        for (int ks = 0; ks < 8; ks++) {
            uint32_t pa[4];
            pa[0] = KP[qw + r][8 * ks + c];
            pa[1] = KP[qw + r + 8][8 * ks + c];
            pa[2] = KP[qw + r][8 * ks + c + 4];
            pa[3] = KP[qw + r + 8][8 * ks + c + 4];
#pragma unroll
            for (int nb = 0; nb < 8; nb++) {
                uint32_t bb[2];
                bb[0] = Vs[8 * ks + c][8 * nb + r];
                bb[1] = Vs[8 * ks + c + 4][8 * nb + r];
                mma8(oacc[nb], pa, bb);
            }
        }
    }

    // finalize
    const float inv0 = 1.0f / l0, inv1 = 1.0f / l1;
    const int n0_ = q0 + qw + r;
#pragma unroll
    for (int nb = 0; nb < 8; nb++) {
        int d = 8 * nb + 2 * c;
        float2 v0; v0.x = oacc[nb][0] * inv0; v0.y = oacc[nb][1] * inv0;
        *(float2*)&out[((size_t)b * N + n0_) * HD + h * D + d] = v0;
        float2 v1; v1.x = oacc[nb][2] * inv1; v1.y = oacc[nb][3] * inv1;
        *(float2*)&out[((size_t)b * N + n0_ + 8) * HD + h * D + d] = v1;
    }
}

extern "C" void kernel_launch(void* const* d_in, const int* in_sizes, int n_in,
                              void* d_out, int out_size)
{
    (void)in_sizes; (void)n_in; (void)out_size;
    const float* hs   = (const float*)d_in[0];
    const float* w    = (const float*)d_in[1];
    const float* qb   = (const float*)d_in[2];
    const float* vb   = (const float*)d_in[3];
    const float* rel  = (const float*)d_in[4];
    const float* rel2 = (const float*)d_in[5];
    const int*   mask = (const int*)d_in[6];
    float* out = (float*)d_out;

    bias_kernel<<<(H * N * N) / (256 * 4), 256>>>(rel, rel2);

    dim3 g1(3 * HD / 128, (B * N) / 128);        // (24, 64)
    qkv_kernel<<<g1, 256>>>(hs, w, qb, vb);

    dim3 g2(N / 64, H, B);                       // (16, 16, 8)
    attn_kernel<<<g2, 128>>>(mask, out);
}

// round 5
// speedup vs baseline: 1.9435x; 1.0037x over previous
#include <cuda_runtime.h>
#include <math.h>
#include <stdint.h>

#define B 8
#define N 1024
#define H 16
#define D 64
#define HD 1024

// Scratch (allocation-free)
__device__ float g_Q[B * H * N * D];
__device__ float g_K[B * H * N * D];
__device__ float g_V[B * H * N * D];
__device__ float g_RB[H * N * N];

__device__ __forceinline__ uint32_t f2tf(float f) {
    uint32_t u;
    asm("cvt.rna.tf32.f32 %0, %1;" : "=r"(u) : "f"(f));
    return u;
}

__device__ __forceinline__ void mma8(float* d, const uint32_t* a, const uint32_t* b) {
    asm volatile(
        "mma.sync.aligned.m16n8k8.row.col.f32.tf32.tf32.f32 "
        "{%0,%1,%2,%3}, {%4,%5,%6,%7}, {%8,%9}, {%0,%1,%2,%3};"
        : "+f"(d[0]), "+f"(d[1]), "+f"(d[2]), "+f"(d[3])
        : "r"(a[0]), "r"(a[1]), "r"(a[2]), "r"(a[3]), "r"(b[0]), "r"(b[1]));
}

#define STS128V(addr, u) asm volatile("st.shared.v4.b32 [%0], {%1,%2,%3,%4};" \
    :: "r"(addr), "r"((u).x), "r"((u).y), "r"((u).z), "r"((u).w) : "memory")

__device__ __forceinline__ uint32_t smem_u32(const void* p) {
    uint32_t a;
    asm("{ .reg .u64 t; cvta.to.shared.u64 t, %1; cvt.u32.u64 %0, t; }"
        : "=r"(a) : "l"(p));
    return a;
}

// ---------------------------------------------------------------------------
// Kernel 0: combined bias = rel_pos + rel_2d_pos
// ---------------------------------------------------------------------------
__global__ __launch_bounds__(256) void bias_kernel(
    const float* __restrict__ rel, const float* __restrict__ rel2)
{
    size_t i = ((size_t)blockIdx.x * 256 + threadIdx.x) * 4;
    float4 a = *(const float4*)&rel[i];
    float4 b = *(const float4*)&rel2[i];
    a.x += b.x; a.y += b.y; a.z += b.z; a.w += b.w;
    *(float4*)&g_RB[i] = a;
}

// ---------------------------------------------------------------------------
// Kernel 1: QKV projection. D[o][token] = W[o][k] * hs[token][k]^T.
// CTA tile 128(o) x 256(tok), 8 warps, warp tile 64x64, BK=16 double-buffered.
// smem pitch 20 words (conflict-free fragment LDS).
// ---------------------------------------------------------------------------
#define QKV_WS_WORDS (128 * 20)       // per buffer
#define QKV_HS_WORDS (256 * 20)
#define QKV_SMEM_BYTES ((2 * QKV_WS_WORDS + 2 * QKV_HS_WORDS) * 4)   // 60KB

__global__ __launch_bounds__(256) void qkv_kernel(
    const float* __restrict__ hs,   // [8192, 1024]
    const float* __restrict__ w,    // [3072, 1024]
    const float* __restrict__ qb,
    const float* __restrict__ vb)
{
    extern __shared__ uint32_t dyn[];
    uint32_t* Wsm = dyn;                       // [2][128][20]
    uint32_t* Hsm = dyn + 2 * QKV_WS_WORDS;    // [2][256][20]
    const uint32_t WsmA = smem_u32(Wsm);
    const uint32_t HsmA = smem_u32(Hsm);

    const int tid  = threadIdx.x;
    const int lane = tid & 31;
    const int warp = tid >> 5;
    const int wo = (warp >> 2) * 64;   // 0 or 64
    const int wt = (warp & 3) * 64;    // 0..192
    const int o0 = blockIdx.x * 128;
    const int t0 = blockIdx.y * 256;
    const int r = lane >> 2;
    const int c = lane & 3;

    float acc[2][8][4];
#pragma unroll
    for (int mi = 0; mi < 2; mi++)
#pragma unroll
        for (int nj = 0; nj < 8; nj++)
#pragma unroll
            for (int q = 0; q < 4; q++) acc[mi][nj][q] = 0.0f;
    float acc2[2][8][4];
#pragma unroll
    for (int mi = 0; mi < 2; mi++)
#pragma unroll
        for (int nj = 0; nj < 8; nj++)
#pragma unroll
            for (int q = 0; q < 4; q++) acc2[mi][nj][q] = 0.0f;

    // staging registers: A 2 float4, B 4 float4 per chunk
    float4 av[2], bv[4];

    auto fetch = [&](int k0) {
#pragma unroll
        for (int i = 0; i < 2; i++) {
            int slot = tid + 256 * i;
            int row = slot >> 2, c4 = (slot & 3) * 4;
            av[i] = *(const float4*)&w[(size_t)(o0 + row) * HD + k0 + c4];
        }
#pragma unroll
        for (int i = 0; i < 4; i++) {
            int slot = tid + 256 * i;
            int row = slot >> 2, c4 = (slot & 3) * 4;
            bv[i] = *(const float4*)&hs[(size_t)(t0 + row) * HD + k0 + c4];
        }
    };
    auto store = [&](int buf) {
#pragma unroll
        for (int i = 0; i < 2; i++) {
            int slot = tid + 256 * i;
            int row = slot >> 2, c4 = (slot & 3) * 4;
            uint4 u; u.x = f2tf(av[i].x); u.y = f2tf(av[i].y);
            u.z = f2tf(av[i].z); u.w = f2tf(av[i].w);
            STS128V(WsmA + (buf * QKV_WS_WORDS + row * 20 + c4) * 4, u);
        }
#pragma unroll
        for (int i = 0; i < 4; i++) {
            int slot = tid + 256 * i;
            int row = slot >> 2, c4 = (slot & 3) * 4;
            uint4 u; u.x = f2tf(bv[i].x); u.y = f2tf(bv[i].y);
            u.z = f2tf(bv[i].z); u.w = f2tf(bv[i].w);
            STS128V(HsmA + (buf * QKV_HS_WORDS + row * 20 + c4) * 4, u);
        }
    };

    fetch(0);
    store(0);
    __syncthreads();

    for (int kc = 0; kc < 64; kc++) {
        const int buf = kc & 1;
        if (kc < 63) fetch((kc + 1) * 16);

        const uint32_t* Wb = Wsm + buf * QKV_WS_WORDS;
        const uint32_t* Hb = Hsm + buf * QKV_HS_WORDS;
#pragma unroll
        for (int ks = 0; ks < 2; ks++) {
            const int kk = ks * 8;
            uint32_t a[2][4], bb[8][2];
#pragma unroll
            for (int mi = 0; mi < 2; mi++) {
                int row = wo + 32 * mi + r;     // warp tile rows: mi covers 64 via 16-row mma pairs
                a[mi][0] = Wb[(row) * 20 + kk + c];
                a[mi][1] = Wb[(row + 8) * 20 + kk + c];
                a[mi][2] = Wb[(row) * 20 + kk + c + 4];
                a[mi][3] = Wb[(row + 8) * 20 + kk + c + 4];
            }
            uint32_t a2[2][4];
#pragma unroll
            for (int mi = 0; mi < 2; mi++) {
                int row = wo + 32 * mi + 16 + r;
                a2[mi][0] = Wb[(row) * 20 + kk + c];
                a2[mi][1] = Wb[(row + 8) * 20 + kk + c];
                a2[mi][2] = Wb[(row) * 20 + kk + c + 4];
                a2[mi][3] = Wb[(row + 8) * 20 + kk + c + 4];
            }
#pragma unroll
            for (int nj = 0; nj < 8; nj++) {
                int col = wt + 8 * nj + r;
                bb[nj][0] = Hb[(col) * 20 + kk + c];
                bb[nj][1] = Hb[(col) * 20 + kk + c + 4];
            }
#pragma unroll
            for (int mi = 0; mi < 2; mi++)
#pragma unroll
                for (int nj = 0; nj < 8; nj++) {
                    mma8(acc[mi][nj], a[mi], bb[nj]);
                    mma8(acc2[mi][nj], a2[mi], bb[nj]);
                }
        }

        if (kc < 63) {
            store(buf ^ 1);
            __syncthreads();
        }
    }

    // epilogue: scatter with fused biases. rows: wo+32mi(+16 for acc2)+r(+8)
    const int c2 = c * 2;
#pragma unroll
    for (int half = 0; half < 2; half++) {
#pragma unroll
        for (int mi = 0; mi < 2; mi++) {
#pragma unroll
            for (int rr = 0; rr < 2; rr++) {
                int o = o0 + wo + 32 * mi + 16 * half + r + 8 * rr;
                int seg = o >> 10, hd = o & 1023, h = hd >> 6, d = hd & 63;
#pragma unroll
                for (int nj = 0; nj < 8; nj++) {
                    int tok = t0 + wt + 8 * nj + c2;
                    int b_ = tok >> 10, n = tok & 1023;
                    size_t idx = (((size_t)(b_ * H + h)) * N + n) * D + d;
                    const float* ap = half ? acc2[mi][nj] : acc[mi][nj];
                    float v0 = ap[rr * 2 + 0];
                    float v1 = ap[rr * 2 + 1];
                    if (seg == 0) {
                        float qv = qb[hd];
                        g_Q[idx] = (v0 + qv) * 0.125f;
                        g_Q[idx + D] = (v1 + qv) * 0.125f;
                    } else if (seg == 1) {
                        g_K[idx] = v0;
                        g_K[idx + D] = v1;
                    } else {
                        float vv = vb[hd];
                        g_V[idx] = v0 + vv;
                        g_V[idx + D] = v1 + vv;
                    }
                }
            }
        }
    }
}

// ---------------------------------------------------------------------------
// Kernel 2: flash attention, 128 q-rows per CTA, 8 warps (16 q each).
// Dedicated P buffer -> 2 syncthreads per key tile. 16 key tiles of 64.
// ---------------------------------------------------------------------------
#define AT_KS_W (64 * 68)
#define AT_VS_W (64 * 72)
#define AT_PS_W (128 * 68)
#define AT_SMEM_BYTES ((AT_KS_W + AT_VS_W + AT_PS_W) * 4)   // ~69KB

__global__ __launch_bounds__(256) void attn_kernel(
    const int* __restrict__ mask,
    float*     __restrict__ out)
{
    extern __shared__ uint32_t dyn[];
    uint32_t* Ks = dyn;                 // [64][68]
    uint32_t* Vs = dyn + AT_KS_W;       // [64][72]
    uint32_t* Ps = dyn + AT_KS_W + AT_VS_W;   // [128][68]
    const uint32_t KsA = smem_u32(Ks);
    const uint32_t VsA = smem_u32(Vs);
    const uint32_t PsA = smem_u32(Ps);

    const int tid  = threadIdx.x;
    const int lane = tid & 31;
    const int warp = tid >> 5;
    const int q0 = blockIdx.x * 128;
    const int h  = blockIdx.y;
    const int b  = blockIdx.z;
    const int qw = warp * 16;
    const int r = lane >> 2;
    const int c = lane & 3;

    const float* Qg = g_Q + ((size_t)(b * H + h) * N) * D;
    const float* Kg = g_K + ((size_t)(b * H + h) * N) * D;
    const float* Vg = g_V + ((size_t)(b * H + h) * N) * D;
    const float* rb = g_RB + (size_t)h * N * N;
    const int*   mk = mask + b * N;

    // stage Q tile (128 x 64) through Ps, each warp stages its own 16 rows
    {
        int row = tid >> 1;                 // 0..127 (warp w -> rows 16w..16w+15)
        int cb = (tid & 1) * 32;
#pragma unroll
        for (int j = 0; j < 8; j++) {
            float4 v = *(const float4*)&Qg[(size_t)(q0 + row) * D + cb + j * 4];
            uint4 u; u.x = f2tf(v.x); u.y = f2tf(v.y); u.z = f2tf(v.z); u.w = f2tf(v.w);
            STS128V(PsA + (row * 68 + cb + j * 4) * 4, u);
        }
    }
    __syncwarp();

    uint32_t qa[8][4];
#pragma unroll
    for (int ks = 0; ks < 8; ks++) {
        qa[ks][0] = Ps[(qw + r) * 68 + 8 * ks + c];
        qa[ks][1] = Ps[(qw + r + 8) * 68 + 8 * ks + c];
        qa[ks][2] = Ps[(qw + r) * 68 + 8 * ks + c + 4];
        qa[ks][3] = Ps[(qw + r + 8) * 68 + 8 * ks + c + 4];
    }

    float m0v = -INFINITY, m1v = -INFINITY, l0 = 0.0f, l1 = 0.0f;
    float oacc[8][4];
#pragma unroll
    for (int nb = 0; nb < 8; nb++)
#pragma unroll
        for (int q = 0; q < 4; q++) oacc[nb][q] = 0.0f;

    for (int t = 0; t < 16; t++) {
        const int k0 = t * 64;
        __syncthreads();   // all warps finished reading Ks/Vs of prev tile

        // load K, V tiles (64 rows x 64 cols each)
        {
            int row = tid >> 2;             // 0..63
            int cb = (tid & 3) * 16;
#pragma unroll
            for (int j = 0; j < 4; j++) {
                float4 kv = *(const float4*)&Kg[(size_t)(k0 + row) * D + cb + j * 4];
                uint4 u; u.x = f2tf(kv.x); u.y = f2tf(kv.y); u.z = f2tf(kv.z); u.w = f2tf(kv.w);
                STS128V(KsA + (row * 68 + cb + j * 4) * 4, u);
                float4 vv = *(const float4*)&Vg[(size_t)(k0 + row) * D + cb + j * 4];
                uint4 w2; w2.x = f2tf(vv.x); w2.y = f2tf(vv.y); w2.z = f2tf(vv.z); w2.w = f2tf(vv.w);
                STS128V(VsA + (row * 72 + cb + j * 4) * 4, w2);
            }
        }
        __syncthreads();

        // S = Q @ K^T
        float sacc[8][4];
#pragma unroll
        for (int nb = 0; nb < 8; nb++)
#pragma unroll
            for (int q = 0; q < 4; q++) sacc[nb][q] = 0.0f;

#pragma unroll
        for (int ks = 0; ks < 8; ks++) {
            uint32_t bb[8][2];
#pragma unroll
            for (int nb = 0; nb < 8; nb++) {
                bb[nb][0] = Ks[(8 * nb + r) * 68 + 8 * ks + c];
                bb[nb][1] = Ks[(8 * nb + r) * 68 + 8 * ks + c + 4];
            }
#pragma unroll
            for (int nb = 0; nb < 8; nb++) mma8(sacc[nb], qa[ks], bb[nb]);
        }

        // bias + mask + row max
        const int row0 = q0 + qw + r;
        float rmax0 = -INFINITY, rmax1 = -INFINITY;
#pragma unroll
        for (int nb = 0; nb < 8; nb++) {
            int col = k0 + 8 * nb + 2 * c;
            float2 bz0 = *(const float2*)&rb[(size_t)row0 * N + col];
            float2 bz1 = *(const float2*)&rb[(size_t)(row0 + 8) * N + col];
            int2 mm = *(const int2*)&mk[col];
            float s0 = sacc[nb][0] + bz0.x; if (mm.x) s0 = 1e-8f;
            float s1 = sacc[nb][1] + bz0.y; if (mm.y) s1 = 1e-8f;
            float s2 = sacc[nb][2] + bz1.x; if (mm.x) s2 = 1e-8f;
            float s3 = sacc[nb][3] + bz1.y; if (mm.y) s3 = 1e-8f;
            sacc[nb][0] = s0; sacc[nb][1] = s1; sacc[nb][2] = s2; sacc[nb][3] = s3;
            rmax0 = fmaxf(rmax0, fmaxf(s0, s1));
            rmax1 = fmaxf(rmax1, fmaxf(s2, s3));
        }
        rmax0 = fmaxf(rmax0, __shfl_xor_sync(0xffffffffu, rmax0, 1));
        rmax0 = fmaxf(rmax0, __shfl_xor_sync(0xffffffffu, rmax0, 2));
        rmax1 = fmaxf(rmax1, __shfl_xor_sync(0xffffffffu, rmax1, 1));
        rmax1 = fmaxf(rmax1, __shfl_xor_sync(0xffffffffu, rmax1, 2));

        float mn0 = fmaxf(m0v, rmax0), mn1 = fmaxf(m1v, rmax1);
        float sc0 = __expf(m0v - mn0), sc1 = __expf(m1v - mn1);
        m0v = mn0; m1v = mn1;

        float rs0 = 0.0f, rs1 = 0.0f;
#pragma unroll
        for (int nb = 0; nb < 8; nb++) {
            float p0 = __expf(sacc[nb][0] - mn0);
            float p1 = __expf(sacc[nb][1] - mn0);
            float p2 = __expf(sacc[nb][2] - mn1);
            float p3 = __expf(sacc[nb][3] - mn1);
            rs0 += p0 + p1;
            rs1 += p2 + p3;
            int col = 8 * nb + 2 * c;
            Ps[(qw + r) * 68 + col] = f2tf(p0);
            Ps[(qw + r) * 68 + col + 1] = f2tf(p1);
            Ps[(qw + r + 8) * 68 + col] = f2tf(p2);
            Ps[(qw + r + 8) * 68 + col + 1] = f2tf(p3);
        }
        rs0 += __shfl_xor_sync(0xffffffffu, rs0, 1);
        rs0 += __shfl_xor_sync(0xffffffffu, rs0, 2);
        rs1 += __shfl_xor_sync(0xffffffffu, rs1, 1);
        rs1 += __shfl_xor_sync(0xffffffffu, rs1, 2);
        l0 = l0 * sc0 + rs0;
        l1 = l1 * sc1 + rs1;
#pragma unroll
        for (int nb = 0; nb < 8; nb++) {
            oacc[nb][0] *= sc0; oacc[nb][1] *= sc0;
            oacc[nb][2] *= sc1; oacc[nb][3] *= sc1;
        }
        __syncwarp();     // P rows owned per-warp; cross-lane visibility only

        // O += P @ V
#pragma unroll
        for (int ks = 0; ks < 8; ks++) {
            uint32_t pa[4];
            pa[0] = Ps[(qw + r) * 68 + 8 * ks + c];
            pa[1] = Ps[(qw + r + 8) * 68 + 8 * ks + c];
            pa[2] = Ps[(qw + r) * 68 + 8 * ks + c + 4];
            pa[3] = Ps[(qw + r + 8) * 68 + 8 * ks + c + 4];
#pragma unroll
            for (int nb = 0; nb < 8; nb++) {
                uint32_t bb[2];
                bb[0] = Vs[(8 * ks + c) * 72 + 8 * nb + r];
                bb[1] = Vs[(8 * ks + c + 4) * 72 + 8 * nb + r];
                mma8(oacc[nb], pa, bb);
            }
        }
    }

    // finalize
    const float inv0 = 1.0f / l0, inv1 = 1.0f / l1;
    const int n0_ = q0 + qw + r;
#pragma unroll
    for (int nb = 0; nb < 8; nb++) {
        int d = 8 * nb + 2 * c;
        float2 v0; v0.x = oacc[nb][0] * inv0; v0.y = oacc[nb][1] * inv0;
        *(float2*)&out[((size_t)b * N + n0_) * HD + h * D + d] = v0;
        float2 v1; v1.x = oacc[nb][2] * inv1; v1.y = oacc[nb][3] * inv1;
        *(float2*)&out[((size_t)b * N + n0_ + 8) * HD + h * D + d] = v1;
    }
}

extern "C" void kernel_launch(void* const* d_in, const int* in_sizes, int n_in,
                              void* d_out, int out_size)
{
    (void)in_sizes; (void)n_in; (void)out_size;
    const float* hs   = (const float*)d_in[0];
    const float* w    = (const float*)d_in[1];
    const float* qb   = (const float*)d_in[2];
    const float* vb   = (const float*)d_in[3];
    const float* rel  = (const float*)d_in[4];
    const float* rel2 = (const float*)d_in[5];
    const int*   mask = (const int*)d_in[6];
    float* out = (float*)d_out;

    cudaFuncSetAttribute(qkv_kernel,
                         cudaFuncAttributeMaxDynamicSharedMemorySize, QKV_SMEM_BYTES);
    cudaFuncSetAttribute(attn_kernel,
                         cudaFuncAttributeMaxDynamicSharedMemorySize, AT_SMEM_BYTES);

    bias_kernel<<<(H * N * N) / (256 * 4), 256>>>(rel, rel2);

    dim3 g1(3 * HD / 128, (B * N) / 256);        // (24, 32)
    qkv_kernel<<<g1, 256, QKV_SMEM_BYTES>>>(hs, w, qb, vb);

    dim3 g2(N / 128, H, B);                      // (8, 16, 8)
    attn_kernel<<<g2, 256, AT_SMEM_BYTES>>>(mask, out);
}

// round 6
// speedup vs baseline: 3.9776x; 2.0466x over previous
#include <cuda_runtime.h>
#include <cuda_fp16.h>
#include <math.h>
#include <stdint.h>

#define B 8
#define N 1024
#define H 16
#define D 64
#define HD 1024

// Scratch (allocation-free): fp16 Q/K, fp16 V transposed [b][h][d][n], fp32 bias
__device__ __half g_Qh[B * H * N * D];
__device__ __half g_Kh[B * H * N * D];
__device__ __half g_Vt[B * H * D * N];
__device__ float  g_RB[H * N * N];

__device__ __forceinline__ uint32_t f2h2(float lo, float hi) {
    __half2 h = __floats2half2_rn(lo, hi);
    return *(uint32_t*)&h;
}

__device__ __forceinline__ void mma16(float* d, const uint32_t* a, const uint32_t* b) {
    asm volatile(
        "mma.sync.aligned.m16n8k16.row.col.f32.f16.f16.f32 "
        "{%0,%1,%2,%3}, {%4,%5,%6,%7}, {%8,%9}, {%0,%1,%2,%3};"
        : "+f"(d[0]), "+f"(d[1]), "+f"(d[2]), "+f"(d[3])
        : "r"(a[0]), "r"(a[1]), "r"(a[2]), "r"(a[3]), "r"(b[0]), "r"(b[1]));
}

#define STS64V(addr, u) asm volatile("st.shared.v2.b32 [%0], {%1,%2};" \
    :: "r"(addr), "r"((u).x), "r"((u).y) : "memory")
#define STS128V(addr, u) asm volatile("st.shared.v4.b32 [%0], {%1,%2,%3,%4};" \
    :: "r"(addr), "r"((u).x), "r"((u).y), "r"((u).z), "r"((u).w) : "memory")

__device__ __forceinline__ uint32_t smem_u32(const void* p) {
    uint32_t a;
    asm("{ .reg .u64 t; cvta.to.shared.u64 t, %1; cvt.u32.u64 %0, t; }"
        : "=r"(a) : "l"(p));
    return a;
}

// ---------------------------------------------------------------------------
// Kernel 0: combined bias = rel_pos + rel_2d_pos
// ---------------------------------------------------------------------------
__global__ __launch_bounds__(256) void bias_kernel(
    const float* __restrict__ rel, const float* __restrict__ rel2)
{
    size_t i = ((size_t)blockIdx.x * 256 + threadIdx.x) * 4;
    float4 a = *(const float4*)&rel[i];
    float4 b = *(const float4*)&rel2[i];
    a.x += b.x; a.y += b.y; a.z += b.z; a.w += b.w;
    *(float4*)&g_RB[i] = a;
}

// ---------------------------------------------------------------------------
// Kernel 1: QKV projection, fp16 m16n8k16. D[o][token] = W[o][k]*hs[token][k]^T
// CTA 128(o) x 256(tok), 8 warps, warp tile 64x64, BK=16 double-buffered.
// smem pitch 12 words (8 data half2-words + 4 pad): conflict-free frag LDS.
// ---------------------------------------------------------------------------
#define QKV_PITCH 12
#define QKV_WS (128 * QKV_PITCH)
#define QKV_HS (256 * QKV_PITCH)

__global__ __launch_bounds__(256) void qkv_kernel(
    const float* __restrict__ hs,   // [8192, 1024]
    const float* __restrict__ w,    // [3072, 1024]
    const float* __restrict__ qb,
    const float* __restrict__ vb)
{
    __shared__ uint32_t Wsm[2 * QKV_WS];
    __shared__ uint32_t Hsm[2 * QKV_HS];
    const uint32_t WsmA = smem_u32(Wsm);
    const uint32_t HsmA = smem_u32(Hsm);

    const int tid  = threadIdx.x;
    const int lane = tid & 31;
    const int warp = tid >> 5;
    const int wo = (warp >> 2) * 64;
    const int wt = (warp & 3) * 64;
    const int o0 = blockIdx.x * 128;
    const int t0 = blockIdx.y * 256;
    const int r = lane >> 2;
    const int c = lane & 3;

    float acc[4][8][4];
#pragma unroll
    for (int g = 0; g < 4; g++)
#pragma unroll
        for (int nj = 0; nj < 8; nj++)
#pragma unroll
            for (int q = 0; q < 4; q++) acc[g][nj][q] = 0.0f;

    float4 av[2], bv[4];
    auto fetch = [&](int k0) {
#pragma unroll
        for (int i = 0; i < 2; i++) {
            int slot = tid + 256 * i;
            int row = slot >> 2, f = slot & 3;
            av[i] = *(const float4*)&w[(size_t)(o0 + row) * HD + k0 + 4 * f];
        }
#pragma unroll
        for (int i = 0; i < 4; i++) {
            int slot = tid + 256 * i;
            int row = slot >> 2, f = slot & 3;
            bv[i] = *(const float4*)&hs[(size_t)(t0 + row) * HD + k0 + 4 * f];
        }
    };
    auto store = [&](int buf) {
#pragma unroll
        for (int i = 0; i < 2; i++) {
            int slot = tid + 256 * i;
            int row = slot >> 2, f = slot & 3;
            uint2 u; u.x = f2h2(av[i].x, av[i].y); u.y = f2h2(av[i].z, av[i].w);
            STS64V(WsmA + (buf * QKV_WS + row * QKV_PITCH + 2 * f) * 4, u);
        }
#pragma unroll
        for (int i = 0; i < 4; i++) {
            int slot = tid + 256 * i;
            int row = slot >> 2, f = slot & 3;
            uint2 u; u.x = f2h2(bv[i].x, bv[i].y); u.y = f2h2(bv[i].z, bv[i].w);
            STS64V(HsmA + (buf * QKV_HS + row * QKV_PITCH + 2 * f) * 4, u);
        }
    };

    fetch(0);
    store(0);
    __syncthreads();

    for (int kc = 0; kc < 64; kc++) {
        const int buf = kc & 1;
        if (kc < 63) fetch((kc + 1) * 16);

        const uint32_t* Wb = Wsm + buf * QKV_WS;
        const uint32_t* Hb = Hsm + buf * QKV_HS;
        uint32_t a[4][4], bb[8][2];
#pragma unroll
        for (int g = 0; g < 4; g++) {
            int row = wo + 16 * g + r;
            a[g][0] = Wb[row * QKV_PITCH + c];
            a[g][1] = Wb[(row + 8) * QKV_PITCH + c];
            a[g][2] = Wb[row * QKV_PITCH + c + 4];
            a[g][3] = Wb[(row + 8) * QKV_PITCH + c + 4];
        }
#pragma unroll
        for (int nj = 0; nj < 8; nj++) {
            int col = wt + 8 * nj + r;
            bb[nj][0] = Hb[col * QKV_PITCH + c];
            bb[nj][1] = Hb[col * QKV_PITCH + c + 4];
        }
#pragma unroll
        for (int g = 0; g < 4; g++)
#pragma unroll
            for (int nj = 0; nj < 8; nj++)
                mma16(acc[g][nj], a[g], bb[nj]);

        if (kc < 63) {
            store(buf ^ 1);
            __syncthreads();
        }
    }

    // epilogue: seg uniform per CTA (o0 = bx*128; bx<8:Q, <16:K, else V)
    const int seg = o0 >> 10;
#pragma unroll
    for (int g = 0; g < 4; g++) {
#pragma unroll
        for (int rr = 0; rr < 2; rr++) {
            int o = o0 + wo + 16 * g + r + 8 * rr;
            int hd = o & 1023, h = hd >> 6, d = hd & 63;
            float qv = (seg == 0) ? qb[hd] : ((seg == 2) ? vb[hd] : 0.0f);
#pragma unroll
            for (int nj = 0; nj < 8; nj++) {
                int tok = t0 + wt + 8 * nj + 2 * c;
                int b_ = tok >> 10, n = tok & 1023;
                float v0 = acc[g][nj][2 * rr + 0];
                float v1 = acc[g][nj][2 * rr + 1];
                if (seg == 0) {
                    size_t idx = (((size_t)(b_ * H + h)) * N + n) * D + d;
                    g_Qh[idx]     = __float2half((v0 + qv) * 0.125f);
                    g_Qh[idx + D] = __float2half((v1 + qv) * 0.125f);
                } else if (seg == 1) {
                    size_t idx = (((size_t)(b_ * H + h)) * N + n) * D + d;
                    g_Kh[idx]     = __float2half(v0);
                    g_Kh[idx + D] = __float2half(v1);
                } else {
                    uint32_t* vp = (uint32_t*)g_Vt;
                    vp[(((size_t)(b_ * H + h)) * D + d) * (N / 2) + (n >> 1)] =
                        f2h2(v0 + qv, v1 + qv);
                }
            }
        }
    }
}

// ---------------------------------------------------------------------------
// Kernel 2: flash attention, fp16 m16n8k16. 128 q-rows/CTA, 8 warps.
// 16 key tiles of 64. Pitch-36 smem, conflict-free fragment access.
// ---------------------------------------------------------------------------
#define AT_PITCH 36

__global__ __launch_bounds__(256) void attn_kernel(
    const int* __restrict__ mask,
    float*     __restrict__ out)
{
    __shared__ uint32_t Ks[64 * AT_PITCH];
    __shared__ uint32_t Vt[64 * AT_PITCH];
    __shared__ uint32_t Ps[128 * AT_PITCH];
    const uint32_t KsA = smem_u32(Ks);
    const uint32_t VtA = smem_u32(Vt);
    const uint32_t PsA = smem_u32(Ps);

    const int tid  = threadIdx.x;
    const int lane = tid & 31;
    const int warp = tid >> 5;
    const int q0 = blockIdx.x * 128;
    const int h  = blockIdx.y;
    const int b  = blockIdx.z;
    const int qw = warp * 16;
    const int r = lane >> 2;
    const int c = lane & 3;

    const __half* Qh  = g_Qh + (size_t)(b * H + h) * N * D;
    const __half* Kh  = g_Kh + (size_t)(b * H + h) * N * D;
    const __half* Vth = g_Vt + (size_t)(b * H + h) * D * N;
    const float*  rb  = g_RB + (size_t)h * N * N;
    const int*    mk  = mask + b * N;

    // stage this warp's 16 Q rows into Ps, then lift fragments to registers
#pragma unroll
    for (int i = 0; i < 4; i++) {
        int slot = lane + 32 * i;
        int row16 = slot >> 3, j = slot & 7;
        uint4 v = ((const uint4*)(Qh + (size_t)(q0 + qw + row16) * D))[j];
        STS128V(PsA + ((qw + row16) * AT_PITCH + 4 * j) * 4, v);
    }
    __syncwarp();

    uint32_t qa[4][4];
#pragma unroll
    for (int ks = 0; ks < 4; ks++) {
        qa[ks][0] = Ps[(qw + r) * AT_PITCH + 8 * ks + c];
        qa[ks][1] = Ps[(qw + r + 8) * AT_PITCH + 8 * ks + c];
        qa[ks][2] = Ps[(qw + r) * AT_PITCH + 8 * ks + c + 4];
        qa[ks][3] = Ps[(qw + r + 8) * AT_PITCH + 8 * ks + c + 4];
    }

    float m0v = -INFINITY, m1v = -INFINITY, l0 = 0.0f, l1 = 0.0f;
    float oacc[8][4];
#pragma unroll
    for (int nb = 0; nb < 8; nb++)
#pragma unroll
        for (int q = 0; q < 4; q++) oacc[nb][q] = 0.0f;

    for (int t = 0; t < 16; t++) {
        const int k0 = t * 64;
        __syncthreads();   // prior tile's Ks/Vt reads complete

        // load K tile [key][d] and V tile (pre-transposed [d][key])
#pragma unroll
        for (int i = 0; i < 2; i++) {
            int slot = tid + 256 * i;
            int row = slot >> 3, j = slot & 7;
            uint4 kv = ((const uint4*)(Kh + (size_t)(k0 + row) * D))[j];
            STS128V(KsA + (row * AT_PITCH + 4 * j) * 4, kv);
            uint4 vv = ((const uint4*)(Vth + (size_t)row * N + k0))[j];
            STS128V(VtA + (row * AT_PITCH + 4 * j) * 4, vv);
        }
        __syncthreads();

        // S = Q @ K^T
        float sacc[8][4];
#pragma unroll
        for (int nb = 0; nb < 8; nb++)
#pragma unroll
            for (int q = 0; q < 4; q++) sacc[nb][q] = 0.0f;

#pragma unroll
        for (int ks = 0; ks < 4; ks++) {
            uint32_t bb[8][2];
#pragma unroll
            for (int nb = 0; nb < 8; nb++) {
                bb[nb][0] = Ks[(8 * nb + r) * AT_PITCH + 8 * ks + c];
                bb[nb][1] = Ks[(8 * nb + r) * AT_PITCH + 8 * ks + c + 4];
            }
#pragma unroll
            for (int nb = 0; nb < 8; nb++) mma16(sacc[nb], qa[ks], bb[nb]);
        }

        // bias + mask + row max
        const int row0 = q0 + qw + r;
        float rmax0 = -INFINITY, rmax1 = -INFINITY;
#pragma unroll
        for (int nb = 0; nb < 8; nb++) {
            int col = k0 + 8 * nb + 2 * c;
            float2 bz0 = *(const float2*)&rb[(size_t)row0 * N + col];
            float2 bz1 = *(const float2*)&rb[(size_t)(row0 + 8) * N + col];
            int2 mm = *(const int2*)&mk[col];
            float s0 = sacc[nb][0] + bz0.x; if (mm.x) s0 = 1e-8f;
            float s1 = sacc[nb][1] + bz0.y; if (mm.y) s1 = 1e-8f;
            float s2 = sacc[nb][2] + bz1.x; if (mm.x) s2 = 1e-8f;
            float s3 = sacc[nb][3] + bz1.y; if (mm.y) s3 = 1e-8f;
            sacc[nb][0] = s0; sacc[nb][1] = s1; sacc[nb][2] = s2; sacc[nb][3] = s3;
            rmax0 = fmaxf(rmax0, fmaxf(s0, s1));
            rmax1 = fmaxf(rmax1, fmaxf(s2, s3));
        }
        rmax0 = fmaxf(rmax0, __shfl_xor_sync(0xffffffffu, rmax0, 1));
        rmax0 = fmaxf(rmax0, __shfl_xor_sync(0xffffffffu, rmax0, 2));
        rmax1 = fmaxf(rmax1, __shfl_xor_sync(0xffffffffu, rmax1, 1));
        rmax1 = fmaxf(rmax1, __shfl_xor_sync(0xffffffffu, rmax1, 2));

        float mn0 = fmaxf(m0v, rmax0), mn1 = fmaxf(m1v, rmax1);
        float sc0 = __expf(m0v - mn0), sc1 = __expf(m1v - mn1);
        m0v = mn0; m1v = mn1;

        float rs0 = 0.0f, rs1 = 0.0f;
#pragma unroll
        for (int nb = 0; nb < 8; nb++) {
            float p0 = __expf(sacc[nb][0] - mn0);
            float p1 = __expf(sacc[nb][1] - mn0);
            float p2 = __expf(sacc[nb][2] - mn1);
            float p3 = __expf(sacc[nb][3] - mn1);
            rs0 += p0 + p1;
            rs1 += p2 + p3;
            Ps[(qw + r) * AT_PITCH + 4 * nb + c]     = f2h2(p0, p1);
            Ps[(qw + r + 8) * AT_PITCH + 4 * nb + c] = f2h2(p2, p3);
        }
        rs0 += __shfl_xor_sync(0xffffffffu, rs0, 1);
        rs0 += __shfl_xor_sync(0xffffffffu, rs0, 2);
        rs1 += __shfl_xor_sync(0xffffffffu, rs1, 1);
        rs1 += __shfl_xor_sync(0xffffffffu, rs1, 2);
        l0 = l0 * sc0 + rs0;
        l1 = l1 * sc1 + rs1;
#pragma unroll
        for (int nb = 0; nb < 8; nb++) {
            oacc[nb][0] *= sc0; oacc[nb][1] *= sc0;
            oacc[nb][2] *= sc1; oacc[nb][3] *= sc1;
        }
        __syncwarp();     // P rows owned per-warp

        // O += P @ V
#pragma unroll
        for (int ks = 0; ks < 4; ks++) {
            uint32_t pa[4];
            pa[0] = Ps[(qw + r) * AT_PITCH + 8 * ks + c];
            pa[1] = Ps[(qw + r + 8) * AT_PITCH + 8 * ks + c];
            pa[2] = Ps[(qw + r) * AT_PITCH + 8 * ks + c + 4];
            pa[3] = Ps[(qw + r + 8) * AT_PITCH + 8 * ks + c + 4];
#pragma unroll
            for (int nb = 0; nb < 8; nb++) {
                uint32_t bb[2];
                bb[0] = Vt[(8 * nb + r) * AT_PITCH + 8 * ks + c];
                bb[1] = Vt[(8 * nb + r) * AT_PITCH + 8 * ks + c + 4];
                mma16(oacc[nb], pa, bb);
            }
        }
    }

    // finalize
    const float inv0 = 1.0f / l0, inv1 = 1.0f / l1;
    const int n0_ = q0 + qw + r;
#pragma unroll
    for (int nb = 0; nb < 8; nb++) {
        int d = 8 * nb + 2 * c;
        float2 v0; v0.x = oacc[nb][0] * inv0; v0.y = oacc[nb][1] * inv0;
        *(float2*)&out[((size_t)b * N + n0_) * HD + h * D + d] = v0;
        float2 v1; v1.x = oacc[nb][2] * inv1; v1.y = oacc[nb][3] * inv1;
        *(float2*)&out[((size_t)b * N + n0_ + 8) * HD + h * D + d] = v1;
    }
}

extern "C" void kernel_launch(void* const* d_in, const int* in_sizes, int n_in,
                              void* d_out, int out_size)
{
    (void)in_sizes; (void)n_in; (void)out_size;
    const float* hs   = (const float*)d_in[0];
    const float* w    = (const float*)d_in[1];
    const float* qb   = (const float*)d_in[2];
    const float* vb   = (const float*)d_in[3];
    const float* rel  = (const float*)d_in[4];
    const float* rel2 = (const float*)d_in[5];
    const int*   mask = (const int*)d_in[6];
    float* out = (float*)d_out;

    bias_kernel<<<(H * N * N) / (256 * 4), 256>>>(rel, rel2);

    dim3 g1(3 * HD / 128, (B * N) / 256);        // (24, 32)
    qkv_kernel<<<g1, 256>>>(hs, w, qb, vb);

    dim3 g2(N / 128, H, B);                      // (8, 16, 8)
    attn_kernel<<<g2, 256>>>(mask, out);
}